// round 13
// baseline (speedup 1.0000x reference)
#include <cuda_runtime.h>
#include <cstdint>

// Problem constants
#define AN 3
#define SSZ 32
#define HH 128
#define WW 128
#define KK (SSZ*HH*WW)        // 524288 spatial positions
#define NN (KK*AN)            // 1572864 total anchors
#define PRE 2000
#define POST 300
#define WORDS 32              // 2048 bits >= PRE
#define PADN 2048             // padded box-array length
#define CAP 4096
#define NMS_T 0.7f
#define TC 0.99834f           // static stash threshold (fast path)
#define PADV 1e30f            // sentinel coord: forces inter==0 against any box

typedef unsigned long long u64;

// ---------------- device state ----------------
__device__ unsigned int g_hist1[65536];
__device__ unsigned int g_hist2[65536];
__device__ int          g_cand_count;      // zero-init; reset by final_k
__device__ u64          g_cand[CAP];
__device__ int          g_rank[CAP];       // zeroed by scan_k each call
__device__ float        g_dstage[CAP*6];   // staged deltas (gathered in scan)

__device__ int   g_order[PRE];
__device__ float g_score[PRE];
__device__ float g_bx1[PADN], g_by1[PADN], g_bz1[PADN];
__device__ float g_bx2[PADN], g_by2[PADN], g_bz2[PADN];
__device__ float g_volv[PADN];
__device__ int   g_valid[PRE];
__device__ u64   g_mask[PRE*WORDS];        // u32 view: [PRE*64]

// ---------------- helpers ----------------
// Stash candidate (flat score-index g, bits b) at slot pos, and gather its 6
// deltas into the staging buffer (scattered loads, issued with high MLP here).
__device__ __forceinline__ void stash_full(const float* __restrict__ deltas,
                                           int pos, int g, unsigned b) {
    int a = g / KK;
    int p = g - a*KK;
    unsigned i = (unsigned)(p*3 + a);
    g_cand[pos] = ((u64)b << 32) | (u64)(0xFFFFFFFFu - i);
    const float* dp = deltas + p + (size_t)(6*a)*KK;
    #pragma unroll
    for (int c = 0; c < 6; ++c)
        g_dstage[pos*6 + c] = dp[(size_t)c*KK];
}

// ---------------- kernels ----------------

// Fast path: one pass over scores (2 float4 per thread, 2 coalesced streams),
// warp-aggregated stash + fused delta gather. Also zeros g_rank and writes
// the mask padding sentinels.
#define SCAN_HALF (NN/8)      // 196608 float4s per stream
__global__ void __launch_bounds__(512) scan_k(const float4* __restrict__ sc,
                                              const float* __restrict__ deltas) {
    int t = blockIdx.x*blockDim.x + threadIdx.x;
    if (t < CAP) g_rank[t] = 0;
    if (t < PADN - PRE) {               // pad slots PRE..2047
        g_bx1[PRE+t] = PADV; g_by1[PRE+t] = PADV; g_bz1[PRE+t] = PADV;
        g_bx2[PRE+t] = PADV; g_by2[PRE+t] = PADV; g_bz2[PRE+t] = PADV;
        g_volv[PRE+t] = 0.0f;
    }
    float4 va = sc[t];
    float4 vb = sc[t + SCAN_HALF];
    unsigned ma0 = __ballot_sync(0xffffffffu, va.x >= TC);
    unsigned ma1 = __ballot_sync(0xffffffffu, va.y >= TC);
    unsigned ma2 = __ballot_sync(0xffffffffu, va.z >= TC);
    unsigned ma3 = __ballot_sync(0xffffffffu, va.w >= TC);
    unsigned mb0 = __ballot_sync(0xffffffffu, vb.x >= TC);
    unsigned mb1 = __ballot_sync(0xffffffffu, vb.y >= TC);
    unsigned mb2 = __ballot_sync(0xffffffffu, vb.z >= TC);
    unsigned mb3 = __ballot_sync(0xffffffffu, vb.w >= TC);
    int ca0 = __popc(ma0), ca1 = __popc(ma1), ca2 = __popc(ma2), ca3 = __popc(ma3);
    int cb0 = __popc(mb0), cb1 = __popc(mb1), cb2 = __popc(mb2), cb3 = __popc(mb3);
    int tot = ca0+ca1+ca2+ca3+cb0+cb1+cb2+cb3;
    if (__ballot_sync(0xffffffffu, tot) == 0) return;   // tot is warp-uniform sum? no — keep simple:
    if (tot == 0) { /* non-stashing lanes still participate in shfl below */ }
    int lane = threadIdx.x & 31;
    int base = 0;
    if (lane == 0 && tot > 0) base = atomicAdd(&g_cand_count, tot);
    base = __shfl_sync(0xffffffffu, base, 0);
    unsigned lt = (1u << lane) - 1u;
    int o = base;
    int offa0 = o + __popc(ma0 & lt); o += ca0;
    int offa1 = o + __popc(ma1 & lt); o += ca1;
    int offa2 = o + __popc(ma2 & lt); o += ca2;
    int offa3 = o + __popc(ma3 & lt); o += ca3;
    int offb0 = o + __popc(mb0 & lt); o += cb0;
    int offb1 = o + __popc(mb1 & lt); o += cb1;
    int offb2 = o + __popc(mb2 & lt); o += cb2;
    int offb3 = o + __popc(mb3 & lt);
    if (va.x >= TC && offa0 < CAP) stash_full(deltas, offa0, 4*t+0, __float_as_uint(va.x));
    if (va.y >= TC && offa1 < CAP) stash_full(deltas, offa1, 4*t+1, __float_as_uint(va.y));
    if (va.z >= TC && offa2 < CAP) stash_full(deltas, offa2, 4*t+2, __float_as_uint(va.z));
    if (va.w >= TC && offa3 < CAP) stash_full(deltas, offa3, 4*t+3, __float_as_uint(va.w));
    int tb = t + SCAN_HALF;
    if (vb.x >= TC && offb0 < CAP) stash_full(deltas, offb0, 4*tb+0, __float_as_uint(vb.x));
    if (vb.y >= TC && offb1 < CAP) stash_full(deltas, offb1, 4*tb+1, __float_as_uint(vb.y));
    if (vb.z >= TC && offb2 < CAP) stash_full(deltas, offb2, 4*tb+2, __float_as_uint(vb.z));
    if (vb.w >= TC && offb3 < CAP) stash_full(deltas, offb3, 4*tb+3, __float_as_uint(vb.w));
}

// Exact fallback, single block. Early-exits (the normal case).
__global__ void __launch_bounds__(1024) fb_all_k(const float* __restrict__ sc,
                                                 const float* __restrict__ deltas) {
    int cnt0 = g_cand_count;
    if (cnt0 >= PRE && cnt0 <= CAP) return;

    __shared__ unsigned cs[1024];
    __shared__ unsigned ss[1024];
    __shared__ unsigned sh_hi, sh_need2, sh_T;
    int t = threadIdx.x;

    for (int o = t; o < 65536; o += 1024) { g_hist1[o] = 0u; g_hist2[o] = 0u; }
    __syncthreads();
    for (int i = t; i < NN; i += 1024) {
        unsigned b = __float_as_uint(sc[i]);
        atomicAdd(&g_hist1[b >> 16], 1u);
    }
    __syncthreads();
    {
        unsigned s = 0;
        for (int m = 0; m < 64; ++m) s += __ldcg(&g_hist1[t*64 + m]);
        cs[t] = s;
        int r = 1023 - t;
        ss[r] = s;
        __syncthreads();
        for (int off = 1; off < 1024; off <<= 1) {
            unsigned v = (r >= off) ? ss[r-off] : 0u;
            __syncthreads();
            ss[r] += v;
            __syncthreads();
        }
        unsigned need = PRE;
        unsigned incl = ss[r];
        unsigned above = incl - cs[t];
        if (above < need && need <= incl) {
            unsigned c = above;
            for (int m = 63; m >= 0; --m) {
                unsigned h = __ldcg(&g_hist1[t*64 + m]);
                if (c + h >= need) { sh_hi = (unsigned)(t*64 + m); sh_need2 = need - c; break; }
                c += h;
            }
        }
    }
    __syncthreads();
    unsigned hi = sh_hi;
    for (int i = t; i < NN; i += 1024) {
        unsigned b = __float_as_uint(sc[i]);
        if ((b >> 16) == hi) atomicAdd(&g_hist2[b & 0xFFFFu], 1u);
    }
    __syncthreads();
    {
        unsigned s = 0;
        for (int m = 0; m < 64; ++m) s += __ldcg(&g_hist2[t*64 + m]);
        cs[t] = s;
        int r = 1023 - t;
        ss[r] = s;
        __syncthreads();
        for (int off = 1; off < 1024; off <<= 1) {
            unsigned v = (r >= off) ? ss[r-off] : 0u;
            __syncthreads();
            ss[r] += v;
            __syncthreads();
        }
        unsigned need = sh_need2;
        unsigned incl = ss[r];
        unsigned above = incl - cs[t];
        if (above < need && need <= incl) {
            unsigned c = above;
            for (int m = 63; m >= 0; --m) {
                unsigned h = __ldcg(&g_hist2[t*64 + m]);
                if (c + h >= need) { sh_T = (hi << 16) | (unsigned)(t*64 + m); break; }
                c += h;
            }
        }
    }
    __syncthreads();
    if (t == 0) g_cand_count = 0;
    __syncthreads();
    unsigned T = sh_T;
    for (int i = t; i < NN; i += 1024) {
        unsigned b = __float_as_uint(sc[i]);
        if (b >= T) {
            int pos = atomicAdd(&g_cand_count, 1);
            if (pos < CAP) stash_full(deltas, pos, i, b);
        }
    }
}

// Partial all-pairs rank: block (bi, q) ranks candidates [bi*256, bi*256+256)
// against j-quarter q of [0, cnt). Partial counts accumulate via atomicAdd.
__global__ void __launch_bounds__(256) rank_part_k() {
    __shared__ u64 tile[256];
    int cnt = g_cand_count; if (cnt > CAP) cnt = CAP;
    int bi = blockIdx.x, q = blockIdx.y;
    if (bi*256 >= cnt) return;
    int i = bi*256 + threadIdx.x;
    u64 my = (i < cnt) ? g_cand[i] : 0xFFFFFFFFFFFFFFFFull;
    int qs = (q * cnt) >> 2;
    int qe = ((q + 1) * cnt) >> 2;
    int rank = 0;
    for (int base = qs; base < qe; base += 256) {
        int j = base + threadIdx.x;
        tile[threadIdx.x] = (j < qe) ? g_cand[j] : 0ull;   // 0 never counts
        __syncthreads();
        #pragma unroll 8
        for (int k = 0; k < 256; ++k) rank += (tile[k] > my) ? 1 : 0;
        __syncthreads();
    }
    if (i < cnt && rank > 0) atomicAdd(&g_rank[i], rank);
}

// Box transform + scatter by exact rank. Deltas come from the L2-hot staging
// buffer (no scattered gathers here).
__global__ void __launch_bounds__(256) transform_k(const float* __restrict__ ii,
                                                   const float* __restrict__ anc) {
    int cnt = g_cand_count; if (cnt > CAP) cnt = CAP;
    int i = blockIdx.x*256 + threadIdx.x;
    if (i >= cnt) return;
    int r = g_rank[i];
    if (r >= PRE) return;
    u64 my = g_cand[i];

    int idx = (int)(0xFFFFFFFFu - (unsigned)(my & 0xFFFFFFFFull));
    float score = __uint_as_float((unsigned)(my >> 32));
    int a = idx % 3;
    int p = idx / 3;
    int w = p % WW;
    int h = (p / WW) % HH;
    int s = p / (WW*HH);
    float shx = 4.0f * (float)w, shy = 4.0f * (float)h, shz = 4.0f * (float)s;
    float x1a = __fadd_rn(shx, anc[a*6+0]);
    float y1a = __fadd_rn(shy, anc[a*6+1]);
    float z1a = __fadd_rn(shz, anc[a*6+2]);
    float x2a = __fadd_rn(shx, anc[a*6+3]);
    float y2a = __fadd_rn(shy, anc[a*6+4]);
    float z2a = __fadd_rn(shz, anc[a*6+5]);
    float ww_ = __fadd_rn(__fsub_rn(x2a, x1a), 1.0f);
    float hh_ = __fadd_rn(__fsub_rn(y2a, y1a), 1.0f);
    float dd_ = __fadd_rn(__fsub_rn(z2a, z1a), 1.0f);
    float cx = __fadd_rn(x1a, __fmul_rn(0.5f, ww_));
    float cy = __fadd_rn(y1a, __fmul_rn(0.5f, hh_));
    float cz = __fadd_rn(z1a, __fmul_rn(0.5f, dd_));
    float dx = g_dstage[i*6+0];
    float dy = g_dstage[i*6+1];
    float dz = g_dstage[i*6+2];
    float dw = g_dstage[i*6+3];
    float dh = g_dstage[i*6+4];
    float dd = g_dstage[i*6+5];
    float pcx = __fadd_rn(__fmul_rn(dx, ww_), cx);
    float pcy = __fadd_rn(__fmul_rn(dy, hh_), cy);
    float pcz = __fadd_rn(__fmul_rn(dz, dd_), cz);
    float pw = __fmul_rn(expf(dw), ww_);
    float ph = __fmul_rn(expf(dh), hh_);
    float pd = __fmul_rn(expf(dd), dd_);
    float slices = ii[0], height = ii[1], width = ii[2], scale = ii[3];
    float wx = __fsub_rn(width, 1.0f);
    float hy = __fsub_rn(height, 1.0f);
    float sz = __fsub_rn(slices, 1.0f);
    float x1 = fminf(fmaxf(__fsub_rn(pcx, __fmul_rn(0.5f, pw)), 0.0f), wx);
    float y1 = fminf(fmaxf(__fsub_rn(pcy, __fmul_rn(0.5f, ph)), 0.0f), hy);
    float z1 = fminf(fmaxf(__fsub_rn(pcz, __fmul_rn(0.5f, pd)), 0.0f), sz);
    float x2 = fminf(fmaxf(__fsub_rn(__fadd_rn(pcx, __fmul_rn(0.5f, pw)), 1.0f), 0.0f), wx);
    float y2 = fminf(fmaxf(__fsub_rn(__fadd_rn(pcy, __fmul_rn(0.5f, ph)), 1.0f), 0.0f), hy);
    float z2 = fminf(fmaxf(__fsub_rn(__fadd_rn(pcz, __fmul_rn(0.5f, pd)), 1.0f), 0.0f), sz);
    float ss_ = __fadd_rn(__fsub_rn(x2, x1), 1.0f);
    float xc = __fadd_rn(x1, __fmul_rn(ss_, 0.5f));
    float yc = __fadd_rn(y1, __fmul_rn(ss_, 0.5f));
    float zc = __fadd_rn(z1, __fmul_rn(ss_, 0.5f));
    float minsz = __fmul_rn(8.0f, scale);
    int valid = (ss_ >= minsz) && (xc < width) && (yc < height) && (zc < slices);
    float vy = __fadd_rn(__fsub_rn(y2, y1), 1.0f);
    float vz = __fadd_rn(__fsub_rn(z2, z1), 1.0f);
    float vol = __fmul_rn(__fmul_rn(ss_, vy), vz);
    g_bx1[r] = x1; g_by1[r] = y1; g_bz1[r] = z1;
    g_bx2[r] = x2; g_by2[r] = y2; g_bz2[r] = z2;
    g_volv[r] = vol;
    g_valid[r] = valid;
    g_order[r] = idx;
    g_score[r] = score;
}

// IoU mask, tiled (128 rows x 32 cols), branchless inner loop: sentinel-padded
// columns produce inter==0, so the only data-dependent branch is the rare
// division. The j>r constraint is one shift-mask applied after the loop.
__global__ void __launch_bounds__(128) mask_k() {
    __shared__ float cx1[32], cy1[32], cz1[32], cx2[32], cy2[32], cz2[32], cv[32];
    int chunk = blockIdx.x;             // col chunk: cols [32*chunk, 32*chunk+32)
    int rb    = blockIdx.y;             // rowblock of 128
    int t = threadIdx.x;
    int r = rb*128 + t;
    int j0 = chunk*32;
    unsigned* m32 = (unsigned*)g_mask;
    if (rb*128 >= j0 + 32) {            // whole block in lower triangle
        if (r < PRE) m32[r*64 + chunk] = 0u;
        return;
    }
    if (t < 32) {
        int c = j0 + t;                 // c < PADN always (chunk < 64)
        cx1[t] = g_bx1[c]; cy1[t] = g_by1[c]; cz1[t] = g_bz1[c];
        cx2[t] = g_bx2[c]; cy2[t] = g_by2[c]; cz2[t] = g_bz2[c];
        cv[t]  = g_volv[c];
    }
    __syncthreads();
    if (r >= PRE) return;
    float x1 = g_bx1[r], y1 = g_by1[r], z1 = g_bz1[r];
    float x2 = g_bx2[r], y2 = g_by2[r], z2 = g_bz2[r];
    float vr = g_volv[r];
    unsigned bits = 0u;
    #pragma unroll 8
    for (int k = 0; k < 32; ++k) {
        float iw = fmaxf(__fadd_rn(__fsub_rn(fminf(x2, cx2[k]), fmaxf(x1, cx1[k])), 1.0f), 0.0f);
        float ih = fmaxf(__fadd_rn(__fsub_rn(fminf(y2, cy2[k]), fmaxf(y1, cy1[k])), 1.0f), 0.0f);
        float id = fmaxf(__fadd_rn(__fsub_rn(fminf(z2, cz2[k]), fmaxf(z1, cz1[k])), 1.0f), 0.0f);
        float inter = __fmul_rn(__fmul_rn(iw, ih), id);
        if (inter > 0.0f) {
            float denom = __fsub_rn(__fadd_rn(vr, cv[k]), inter);
            float iou = __fdiv_rn(inter, denom);
            if (iou > NMS_T) bits |= (1u << k);
        }
    }
    int d = r - j0;                     // j>r mask: keep bits k with j0+k > r
    unsigned jmask = (d < 0) ? 0xFFFFFFFFu : ((d >= 31) ? 0u : (0xFFFFFFFFu << (d+1)));
    m32[r*64 + chunk] = bits & jmask;
}

__device__ __forceinline__ void fill_one(float* out, int i, int pos) {
    int base = pos*7;
    out[base+0] = 0.0f;
    out[base+1] = g_bx1[i];
    out[base+2] = g_by1[i];
    out[base+3] = g_bz1[i];
    out[base+4] = g_bx2[i];
    out[base+5] = g_by2[i];
    out[base+6] = g_bz2[i];
    out[POST*7 + pos] = g_score[i];          // 2100..2399
    out[POST*8 + pos] = (float)g_order[i];   // 2400..2699
    out[POST*9 + pos] = 1.0f;                // 2700..2999
}

// One NMS chunk step: prefetch rows (c+2)*16.. into NXT, decide chunk c from
// CUR (16-bit window on the owning lane), broadcast, OR-tree apply.
#define NMS_STEP(CUR, NXT, C) do {                                          \
    int nbase_ = ((C) + 2) * 16;                                            \
    _Pragma("unroll")                                                       \
    for (int b_ = 0; b_ < 16; ++b_) {                                       \
        int row_ = nbase_ + b_;                                             \
        NXT[b_] = (row_ < PRE) ? g_mask[(size_t)row_*WORDS + lane] : 0ull;  \
    }                                                                       \
    int w_  = ((C) * 16) >> 6;                                              \
    int sh_ = ((C) * 16) & 63;                                              \
    unsigned acc_ = 0u;                                                     \
    if (lane == w_) {                                                       \
        unsigned w16_ = (unsigned)(rm >> sh_) & 0xFFFFu;                    \
        _Pragma("unroll")                                                   \
        for (int b_ = 0; b_ < 16; ++b_) {                                   \
            unsigned vw_ = (unsigned)(CUR[b_] >> sh_) & 0xFFFFu;            \
            unsigned sup_ = (w16_ >> b_) & 1u;                              \
            acc_ |= (sup_ ^ 1u) << b_;                                      \
            w16_ |= sup_ ? 0u : vw_;                                        \
        }                                                                   \
    }                                                                       \
    acc_ = __shfl_sync(0xffffffffu, acc_, w_);                              \
    u64 a0_ = (((acc_>>0)&1u)?CUR[0]:0ull)  | (((acc_>>1)&1u)?CUR[1]:0ull)  \
            | (((acc_>>2)&1u)?CUR[2]:0ull)  | (((acc_>>3)&1u)?CUR[3]:0ull); \
    u64 a1_ = (((acc_>>4)&1u)?CUR[4]:0ull)  | (((acc_>>5)&1u)?CUR[5]:0ull)  \
            | (((acc_>>6)&1u)?CUR[6]:0ull)  | (((acc_>>7)&1u)?CUR[7]:0ull); \
    u64 a2_ = (((acc_>>8)&1u)?CUR[8]:0ull)  | (((acc_>>9)&1u)?CUR[9]:0ull)  \
            | (((acc_>>10)&1u)?CUR[10]:0ull)| (((acc_>>11)&1u)?CUR[11]:0ull);\
    u64 a3_ = (((acc_>>12)&1u)?CUR[12]:0ull)| (((acc_>>13)&1u)?CUR[13]:0ull)\
            | (((acc_>>14)&1u)?CUR[14]:0ull)| (((acc_>>15)&1u)?CUR[15]:0ull);\
    rm |= (a0_|a1_) | (a2_|a3_);                                            \
} while (0)

// Merged NMS-reduce + output, 256 threads. Warp 0: serial greedy reduce with
// triple-buffered register prefetch. Warps 1..7 init the output buffer.
__global__ void __launch_bounds__(256) final_k(float* __restrict__ out, int out_size) {
    __shared__ int sc[256];
    __shared__ u64 rw[WORDS];
    int t = threadIdx.x;

    if (t < 32) {
        int lane = t;
        u64 rm = 0ull;
        #pragma unroll
        for (int b = 0; b < 64; ++b) {
            int j = lane*64 + b;
            int inval = (j < PRE) ? (g_valid[j] ? 0 : 1) : 1;
            rm |= ((u64)inval) << b;
        }
        u64 buf0[16], buf1[16], buf2[16];
        #pragma unroll
        for (int b = 0; b < 16; ++b) buf0[b] = g_mask[(size_t)b*WORDS + lane];
        #pragma unroll
        for (int b = 0; b < 16; ++b) buf1[b] = g_mask[(size_t)(16+b)*WORDS + lane];
        for (int c = 0; c < 123; c += 3) {
            NMS_STEP(buf0, buf2, c);
            NMS_STEP(buf1, buf0, c+1);
            NMS_STEP(buf2, buf1, c+2);
        }
        NMS_STEP(buf0, buf2, 123);
        NMS_STEP(buf1, buf0, 124);
        rw[lane] = rm;
    } else {
        for (int o = t - 32; o < POST*8; o += 224) if (o < out_size) out[o] = 0.0f;
        for (int o = t - 32; o < POST; o += 224) {
            if (POST*8 + o < out_size) out[POST*8 + o] = -1.0f;
            if (POST*9 + o < out_size) out[POST*9 + o] = 0.0f;
        }
    }
    __syncthreads();

    int kk[8];
    int ksum = 0;
    #pragma unroll
    for (int c = 0; c < 8; ++c) {
        int i = 8*t + c;
        int k = 0;
        if (i < PRE) k = (g_valid[i] && !((rw[i>>6] >> (i & 63)) & 1ull)) ? 1 : 0;
        kk[c] = k;
        ksum += k;
    }
    sc[t] = ksum;
    __syncthreads();
    for (int off = 1; off < 256; off <<= 1) {
        int v = (t >= off) ? sc[t-off] : 0;
        __syncthreads();
        sc[t] += v;
        __syncthreads();
    }
    int pos = sc[t] - ksum;
    if (out_size >= POST*10) {
        #pragma unroll
        for (int c = 0; c < 8; ++c) {
            if (kk[c] && pos < POST) fill_one(out, 8*t + c, pos);
            pos += kk[c];
        }
    }
    if (t == 0) g_cand_count = 0;   // clean state for next graph replay
}

// ---------------- launch ----------------
extern "C" void kernel_launch(void* const* d_in, const int* in_sizes, int n_in,
                              void* d_out, int out_size) {
    const float* scores  = (const float*)d_in[0];
    const float* deltas  = (const float*)d_in[1];
    const float* iminfo  = (const float*)d_in[2];
    const float* anchors = (const float*)d_in[3];
    float* out = (float*)d_out;

    scan_k<<<SCAN_HALF/512, 512>>>((const float4*)scores, deltas);
    fb_all_k<<<1, 1024>>>(scores, deltas);             // early-exits normally
    rank_part_k<<<dim3(CAP/256, 4), 256>>>();
    transform_k<<<CAP/256, 256>>>(iminfo, anchors);
    mask_k<<<dim3(64, (PRE + 127)/128), 128>>>();
    final_k<<<1, 256>>>(out, out_size);
}